// round 3
// baseline (speedup 1.0000x reference)
#include <cuda_runtime.h>
#include <cuda_fp16.h>
#include <cuda_bf16.h>

#define N_NODES 100000
#define N_EDGES 1600000
#define F 64
#define NCLS 16
#define NEG_SLOPE 0.01f

#define SCAN_BLK 1024
#define SCAN_NB ((N_NODES + SCAN_BLK - 1) / SCAN_BLK)   // 98

typedef unsigned long long ull;

// ---------------- scratch (device globals; zero at module load) --------------
__device__ int    g_deg[N_NODES];      // histogram; restored to 0 each call
__device__ int    g_off[N_NODES + 1];
__device__ int    g_cursor[N_NODES];
__device__ int    g_csr[N_EDGES];
__device__ int    g_bsum[SCAN_NB];
__device__ __half g_P[(size_t)N_NODES * F];   // fp16 messages
__device__ float  g_H[(size_t)N_NODES * F];   // layer-1 output (fp32)

// ---------------- f32x2 helpers (sm_100+ packed fp32 FMA) --------------------
__device__ __forceinline__ void ffma2(ull& d, ull a, ull b) {
    asm("fma.rn.f32x2 %0, %1, %2, %0;" : "+l"(d) : "l"(a), "l"(b));
}
__device__ __forceinline__ ull pack2(float x) {
    ull r; asm("mov.b64 %0, {%1, %1};" : "=l"(r) : "f"(x)); return r;
}
__device__ __forceinline__ float2 unpack2(ull a) {
    float2 r; asm("mov.b64 {%0, %1}, %2;" : "=f"(r.x), "=f"(r.y) : "l"(a)); return r;
}

// ---------------- CSR build --------------------------------------------------
__global__ void hist_kernel(const int4* __restrict__ dst4) {
    int i = blockIdx.x * blockDim.x + threadIdx.x;
    if (i < N_EDGES / 4) {
        int4 d = __ldg(&dst4[i]);
        atomicAdd(&g_deg[d.x], 1);
        atomicAdd(&g_deg[d.y], 1);
        atomicAdd(&g_deg[d.z], 1);
        atomicAdd(&g_deg[d.w], 1);
    }
}

// reads g_deg (and restores it to zero for the next call), writes block-local
// exclusive prefix into g_off, block sums into g_bsum
__global__ __launch_bounds__(SCAN_BLK) void scan1_kernel() {
    __shared__ int s[SCAN_BLK];
    int t = threadIdx.x;
    int idx = blockIdx.x * SCAN_BLK + t;
    int val = 0;
    if (idx < N_NODES) { val = g_deg[idx]; g_deg[idx] = 0; }
    s[t] = val;
    __syncthreads();
    #pragma unroll
    for (int o = 1; o < SCAN_BLK; o <<= 1) {
        int x = (t >= o) ? s[t - o] : 0;
        __syncthreads();
        s[t] += x;
        __syncthreads();
    }
    if (idx < N_NODES) g_off[idx] = s[t] - val;
    if (t == SCAN_BLK - 1) g_bsum[blockIdx.x] = s[t];
}

// add block-sum prefix, init cursors
__global__ __launch_bounds__(256) void scan3_kernel() {
    __shared__ int sb[SCAN_NB];
    __shared__ int s_carry;
    int t = threadIdx.x;
    if (t < SCAN_NB) sb[t] = g_bsum[t];
    __syncthreads();
    if (t == 0) {
        int myblk = (blockIdx.x * 256) / SCAN_BLK;
        int c = 0;
        for (int i = 0; i < myblk; i++) c += sb[i];
        s_carry = c;
    }
    __syncthreads();
    int i = blockIdx.x * 256 + t;
    if (i < N_NODES) {
        int o = g_off[i] + s_carry;
        g_off[i] = o;
        g_cursor[i] = o;
    }
    if (i == 0) g_off[N_NODES] = N_EDGES;
}

__global__ void fill_csr_kernel(const int4* __restrict__ src4,
                                const int4* __restrict__ dst4) {
    int i = blockIdx.x * blockDim.x + threadIdx.x;
    if (i < N_EDGES / 4) {
        int4 s = __ldg(&src4[i]);
        int4 d = __ldg(&dst4[i]);
        g_csr[atomicAdd(&g_cursor[d.x], 1)] = s.x;
        g_csr[atomicAdd(&g_cursor[d.y], 1)] = s.y;
        g_csr[atomicAdd(&g_cursor[d.z], 1)] = s.z;
        g_csr[atomicAdd(&g_cursor[d.w], 1)] = s.w;
    }
}

// -------- GEMM: P[N,64] = relu(X[N,64] @ W[64,64] + b), fp16 output ----------
__global__ __launch_bounds__(256) void gemm_pool_kernel(
        const float* __restrict__ X, const float* __restrict__ W,
        const float* __restrict__ b, __half* __restrict__ Y) {
    __shared__ ulonglong2 sW[F * F / 4];
    __shared__ ull sb[F / 2];
    int t = threadIdx.x;
    const ulonglong2* W2 = (const ulonglong2*)W;
    #pragma unroll
    for (int i = 0; i < F * F / 4; i += 256) sW[i + t] = W2[i + t];
    if (t < F / 2) sb[t] = ((const ull*)b)[t];
    __syncthreads();

    int r = blockIdx.x * 256 + t;
    if (r >= N_NODES) return;

    ull acc[F / 2];
    #pragma unroll
    for (int j = 0; j < F / 2; j++) acc[j] = sb[j];

    const float4* xr = (const float4*)(X + (size_t)r * F);
    #pragma unroll
    for (int k4 = 0; k4 < F / 4; k4++) {
        float4 xv = __ldg(&xr[k4]);
        float xs[4] = {xv.x, xv.y, xv.z, xv.w};
        #pragma unroll
        for (int kk = 0; kk < 4; kk++) {
            int k = k4 * 4 + kk;
            ull xk = pack2(xs[kk]);
            #pragma unroll
            for (int j4 = 0; j4 < F / 4; j4++) {
                ulonglong2 w = sW[k * (F / 4) + j4];
                ffma2(acc[2 * j4 + 0], xk, w.x);
                ffma2(acc[2 * j4 + 1], xk, w.y);
            }
        }
    }
    uint4* yr = (uint4*)(Y + (size_t)r * F);
    #pragma unroll
    for (int j8 = 0; j8 < F / 8; j8++) {
        unsigned u[4];
        #pragma unroll
        for (int q = 0; q < 4; q++) {
            float2 v = unpack2(acc[j8 * 4 + q]);
            __half2 h = __floats2half2_rn(fmaxf(v.x, 0.f), fmaxf(v.y, 0.f));
            u[q] = *reinterpret_cast<unsigned*>(&h);
        }
        uint4 o; o.x = u[0]; o.y = u[1]; o.z = u[2]; o.w = u[3];
        yr[j8] = o;
    }
}

// ------- Fused: segment-max pool (fp16) + out-GEMM ---------------------------
// Warp w pools nodes [base+32w, base+32w+32) into padded smem tile, syncwarp,
// then thread-per-row GEMM: Y = act(X@Ws + pooled@Wn + b).
// Dynamic smem: sWs | sWn | sb | spool(256 x 33 half2)
template <int DOUT, int ACT>
__global__ __launch_bounds__(256) void fused_pool_gemm_kernel(
        const __half* __restrict__ P, const float* __restrict__ X,
        const float* __restrict__ Ws, const float* __restrict__ Wn,
        const float* __restrict__ b, float* __restrict__ Y) {
    extern __shared__ char dsm[];
    ulonglong2* sWs  = (ulonglong2*)dsm;
    ulonglong2* sWn  = sWs + F * DOUT / 4;
    ull*        sb   = (ull*)(sWn + F * DOUT / 4);
    __half2*    spool= (__half2*)(sb + DOUT / 2);   // [256][33] padded rows

    int t = threadIdx.x;
    const ulonglong2* Ws2 = (const ulonglong2*)Ws;
    const ulonglong2* Wn2 = (const ulonglong2*)Wn;
    for (int i = t; i < F * DOUT / 4; i += 256) { sWs[i] = Ws2[i]; sWn[i] = Wn2[i]; }
    if (t < DOUT / 2) sb[t] = ((const ull*)b)[t];
    __syncthreads();

    int w = t >> 5, lane = t & 31;
    int base = blockIdx.x * 256;
    const __half2* P2 = (const __half2*)P;

    // ---- pool phase: warp w pools its own 32 rows ----
    for (int j = 0; j < 32; j++) {
        int r = base + w * 32 + j;
        if (r < N_NODES) {
            int s0 = g_off[r];
            int s1 = g_off[r + 1];
            __half2 m = __float2half2_rn(0.f);
            int e = s0;
            for (; e + 4 <= s1; e += 4) {
                int i0 = g_csr[e + 0], i1 = g_csr[e + 1];
                int i2 = g_csr[e + 2], i3 = g_csr[e + 3];
                __half2 a0 = __ldg(&P2[i0 * (F / 2) + lane]);
                __half2 a1 = __ldg(&P2[i1 * (F / 2) + lane]);
                __half2 a2 = __ldg(&P2[i2 * (F / 2) + lane]);
                __half2 a3 = __ldg(&P2[i3 * (F / 2) + lane]);
                m = __hmax2(m, __hmax2(__hmax2(a0, a1), __hmax2(a2, a3)));
            }
            for (; e < s1; e++) {
                int i = g_csr[e];
                m = __hmax2(m, __ldg(&P2[i * (F / 2) + lane]));
            }
            spool[(w * 32 + j) * 33 + lane] = m;
        }
    }
    __syncwarp();

    // ---- GEMM phase: thread t -> row base+t ----
    int r = base + t;
    if (r >= N_NODES) return;

    ull acc[DOUT / 2];
    #pragma unroll
    for (int j = 0; j < DOUT / 2; j++) acc[j] = sb[j];

    const float4* xr = (const float4*)(X + (size_t)r * F);
    #pragma unroll
    for (int k4 = 0; k4 < F / 4; k4++) {
        float4 xv = __ldg(&xr[k4]);
        float xs[4] = {xv.x, xv.y, xv.z, xv.w};
        #pragma unroll
        for (int kk = 0; kk < 4; kk++) {
            int k = k4 * 4 + kk;
            ull xk = pack2(xs[kk]);
            #pragma unroll
            for (int j4 = 0; j4 < DOUT / 4; j4++) {
                ulonglong2 wv = sWs[k * (DOUT / 4) + j4];
                ffma2(acc[2 * j4 + 0], xk, wv.x);
                ffma2(acc[2 * j4 + 1], xk, wv.y);
            }
        }
    }
    // neighbor term from smem pooled row (feats {2k2, 2k2+1} at slot k2)
    #pragma unroll
    for (int k2 = 0; k2 < F / 2; k2++) {
        float2 f = __half22float2(spool[t * 33 + k2]);
        ull xa = pack2(f.x);
        ull xb = pack2(f.y);
        int k0 = 2 * k2, k1 = 2 * k2 + 1;
        #pragma unroll
        for (int j4 = 0; j4 < DOUT / 4; j4++) {
            ulonglong2 wv = sWn[k0 * (DOUT / 4) + j4];
            ffma2(acc[2 * j4 + 0], xa, wv.x);
            ffma2(acc[2 * j4 + 1], xa, wv.y);
        }
        #pragma unroll
        for (int j4 = 0; j4 < DOUT / 4; j4++) {
            ulonglong2 wv = sWn[k1 * (DOUT / 4) + j4];
            ffma2(acc[2 * j4 + 0], xb, wv.x);
            ffma2(acc[2 * j4 + 1], xb, wv.y);
        }
    }
    float4* yr = (float4*)(Y + (size_t)r * DOUT);
    #pragma unroll
    for (int j4 = 0; j4 < DOUT / 4; j4++) {
        float2 v0 = unpack2(acc[2 * j4 + 0]);
        float2 v1 = unpack2(acc[2 * j4 + 1]);
        float a0 = v0.x, a1 = v0.y, a2 = v1.x, a3 = v1.y;
        if (ACT == 1) {
            a0 = (a0 >= 0.f) ? a0 : NEG_SLOPE * a0;
            a1 = (a1 >= 0.f) ? a1 : NEG_SLOPE * a1;
            a2 = (a2 >= 0.f) ? a2 : NEG_SLOPE * a2;
            a3 = (a3 >= 0.f) ? a3 : NEG_SLOPE * a3;
        }
        float4 o; o.x = a0; o.y = a1; o.z = a2; o.w = a3;
        yr[j4] = o;
    }
}

// ---------------- launch -----------------------------------------------------
static inline int fused_smem_bytes(int dout) {
    return 2 * (F * dout * 4) + dout * 4 + 256 * 33 * 4;
}

extern "C" void kernel_launch(void* const* d_in, const int* in_sizes, int n_in,
                              void* d_out, int out_size) {
    const float* in_feat = (const float*)d_in[0];
    const int*   src     = (const int*)d_in[1];
    const int*   dst     = (const int*)d_in[2];
    const float* W_pool1 = (const float*)d_in[3];
    const float* b_pool1 = (const float*)d_in[4];
    const float* W_self1 = (const float*)d_in[5];
    const float* W_neigh1= (const float*)d_in[6];
    const float* bias1   = (const float*)d_in[7];
    const float* W_pool2 = (const float*)d_in[8];
    const float* b_pool2 = (const float*)d_in[9];
    const float* W_self2 = (const float*)d_in[10];
    const float* W_neigh2= (const float*)d_in[11];
    const float* bias2   = (const float*)d_in[12];
    float* out = (float*)d_out;

    __half* dP; float* dH;
    cudaGetSymbolAddress((void**)&dP, g_P);
    cudaGetSymbolAddress((void**)&dH, g_H);

    const int EB4   = (N_EDGES / 4 + 255) / 256;
    const int NB256 = (N_NODES + 255) / 256;

    int smemB = fused_smem_bytes(64);
    int smemC = fused_smem_bytes(16);
    cudaFuncSetAttribute(fused_pool_gemm_kernel<64, 1>,
                         cudaFuncAttributeMaxDynamicSharedMemorySize, smemB);
    cudaFuncSetAttribute(fused_pool_gemm_kernel<16, 0>,
                         cudaFuncAttributeMaxDynamicSharedMemorySize, smemC);

    // ---- CSR build (g_deg is zero on entry; scan1 restores it) ----
    hist_kernel<<<EB4, 256>>>((const int4*)dst);
    scan1_kernel<<<SCAN_NB, SCAN_BLK>>>();
    scan3_kernel<<<NB256, 256>>>();
    fill_csr_kernel<<<EB4, 256>>>((const int4*)src, (const int4*)dst);

    // ---- layer 1 ----
    gemm_pool_kernel<<<NB256, 256>>>(in_feat, W_pool1, b_pool1, dP);
    fused_pool_gemm_kernel<64, 1><<<NB256, 256, smemB>>>(
        dP, in_feat, W_self1, W_neigh1, bias1, dH);

    // ---- layer 2 ----
    gemm_pool_kernel<<<NB256, 256>>>(dH, W_pool2, b_pool2, dP);
    fused_pool_gemm_kernel<16, 0><<<NB256, 256, smemC>>>(
        dP, dH, W_self2, W_neigh2, bias2, out);
}

// round 4
// speedup vs baseline: 1.3946x; 1.3946x over previous
#include <cuda_runtime.h>
#include <cuda_fp16.h>
#include <cuda_bf16.h>

#define N_NODES 100000
#define N_EDGES 1600000
#define F 64
#define NCLS 16
#define NEG_SLOPE 0.01f

#define SCAN_BLK 1024
#define SCAN_NB ((N_NODES + SCAN_BLK - 1) / SCAN_BLK)   // 98

#define EB4   ((N_EDGES / 4 + 255) / 256)   // 1563 hist/fill blocks
#define NB256 ((N_NODES + 255) / 256)       // 391 node blocks

typedef unsigned long long ull;

// ---------------- scratch (device globals; zero at module load) --------------
__device__ int    g_deg[N_NODES];      // histogram; restored to 0 each call
__device__ int    g_off[N_NODES + 1];
__device__ int    g_cursor[N_NODES];
__device__ int    g_csr[N_EDGES];
__device__ int    g_bsum[SCAN_NB];
__device__ __half g_P[(size_t)N_NODES * F];   // fp16 messages
__device__ __half g_Pl[(size_t)N_NODES * F];  // fp16 pooled (exact)
__device__ float  g_H[(size_t)N_NODES * F];   // layer-1 output (fp32)

// ---------------- f32x2 helpers (sm_100+ packed fp32 FMA) --------------------
__device__ __forceinline__ void ffma2(ull& d, ull a, ull b) {
    asm("fma.rn.f32x2 %0, %1, %2, %0;" : "+l"(d) : "l"(a), "l"(b));
}
__device__ __forceinline__ ull pack2(float x) {
    ull r; asm("mov.b64 %0, {%1, %1};" : "=l"(r) : "f"(x)); return r;
}
__device__ __forceinline__ float2 unpack2(ull a) {
    float2 r; asm("mov.b64 {%0, %1}, %2;" : "=f"(r.x), "=f"(r.y) : "l"(a)); return r;
}

// ---------- GEMM body: acc[F/2] (f32x2) += row(X) @ W(smem) ------------------
__device__ __forceinline__ void gemm_row_f64(const float4* __restrict__ xr,
                                             const ulonglong2* __restrict__ sW,
                                             ull* acc) {
    #pragma unroll
    for (int k4 = 0; k4 < F / 4; k4++) {
        float4 xv = __ldg(&xr[k4]);
        float xs[4] = {xv.x, xv.y, xv.z, xv.w};
        #pragma unroll
        for (int kk = 0; kk < 4; kk++) {
            int k = k4 * 4 + kk;
            ull xk = pack2(xs[kk]);
            #pragma unroll
            for (int j4 = 0; j4 < F / 4; j4++) {
                ulonglong2 w = sW[k * (F / 4) + j4];
                ffma2(acc[2 * j4 + 0], xk, w.x);
                ffma2(acc[2 * j4 + 1], xk, w.y);
            }
        }
    }
}

// ------- K1: merged edge histogram + layer-1 pool GEMM -----------------------
// Blocks [0, EB4): histogram dst into g_deg.
// Blocks [EB4, EB4+NB256): P = relu(X @ Wp + b) -> fp16.
__global__ __launch_bounds__(256) void hist_gemm_kernel(
        const int4* __restrict__ dst4,
        const float* __restrict__ X, const float* __restrict__ W,
        const float* __restrict__ b, __half* __restrict__ Y) {
    __shared__ ulonglong2 sW[F * F / 4];
    __shared__ ull sb[F / 2];
    int t = threadIdx.x;

    if (blockIdx.x < EB4) {
        int i = blockIdx.x * 256 + t;
        if (i < N_EDGES / 4) {
            int4 d = __ldg(&dst4[i]);
            atomicAdd(&g_deg[d.x], 1);
            atomicAdd(&g_deg[d.y], 1);
            atomicAdd(&g_deg[d.z], 1);
            atomicAdd(&g_deg[d.w], 1);
        }
        return;
    }

    const ulonglong2* W2 = (const ulonglong2*)W;
    #pragma unroll
    for (int i = 0; i < F * F / 4; i += 256) sW[i + t] = W2[i + t];
    if (t < F / 2) sb[t] = ((const ull*)b)[t];
    __syncthreads();

    int r = (blockIdx.x - EB4) * 256 + t;
    if (r >= N_NODES) return;

    ull acc[F / 2];
    #pragma unroll
    for (int j = 0; j < F / 2; j++) acc[j] = sb[j];
    gemm_row_f64((const float4*)(X + (size_t)r * F), sW, acc);

    uint4* yr = (uint4*)(Y + (size_t)r * F);
    #pragma unroll
    for (int j8 = 0; j8 < F / 8; j8++) {
        unsigned u[4];
        #pragma unroll
        for (int q = 0; q < 4; q++) {
            float2 v = unpack2(acc[j8 * 4 + q]);
            __half2 h = __floats2half2_rn(fmaxf(v.x, 0.f), fmaxf(v.y, 0.f));
            u[q] = *reinterpret_cast<unsigned*>(&h);
        }
        uint4 o; o.x = u[0]; o.y = u[1]; o.z = u[2]; o.w = u[3];
        yr[j8] = o;
    }
}

// ---------------- plain pool GEMM (layer 2): P = relu(H @ Wp + b) ------------
__global__ __launch_bounds__(256) void gemm_pool_kernel(
        const float* __restrict__ X, const float* __restrict__ W,
        const float* __restrict__ b, __half* __restrict__ Y) {
    __shared__ ulonglong2 sW[F * F / 4];
    __shared__ ull sb[F / 2];
    int t = threadIdx.x;
    const ulonglong2* W2 = (const ulonglong2*)W;
    #pragma unroll
    for (int i = 0; i < F * F / 4; i += 256) sW[i + t] = W2[i + t];
    if (t < F / 2) sb[t] = ((const ull*)b)[t];
    __syncthreads();

    int r = blockIdx.x * 256 + t;
    if (r >= N_NODES) return;

    ull acc[F / 2];
    #pragma unroll
    for (int j = 0; j < F / 2; j++) acc[j] = sb[j];
    gemm_row_f64((const float4*)(X + (size_t)r * F), sW, acc);

    uint4* yr = (uint4*)(Y + (size_t)r * F);
    #pragma unroll
    for (int j8 = 0; j8 < F / 8; j8++) {
        unsigned u[4];
        #pragma unroll
        for (int q = 0; q < 4; q++) {
            float2 v = unpack2(acc[j8 * 4 + q]);
            __half2 h = __floats2half2_rn(fmaxf(v.x, 0.f), fmaxf(v.y, 0.f));
            u[q] = *reinterpret_cast<unsigned*>(&h);
        }
        uint4 o; o.x = u[0]; o.y = u[1]; o.z = u[2]; o.w = u[3];
        yr[j8] = o;
    }
}

// ---------------- CSR scan + fill --------------------------------------------
__global__ __launch_bounds__(SCAN_BLK) void scan1_kernel() {
    __shared__ int s[SCAN_BLK];
    int t = threadIdx.x;
    int idx = blockIdx.x * SCAN_BLK + t;
    int val = 0;
    if (idx < N_NODES) { val = g_deg[idx]; g_deg[idx] = 0; }
    s[t] = val;
    __syncthreads();
    #pragma unroll
    for (int o = 1; o < SCAN_BLK; o <<= 1) {
        int x = (t >= o) ? s[t - o] : 0;
        __syncthreads();
        s[t] += x;
        __syncthreads();
    }
    if (idx < N_NODES) g_off[idx] = s[t] - val;
    if (t == SCAN_BLK - 1) g_bsum[blockIdx.x] = s[t];
}

__global__ __launch_bounds__(256) void scan3_kernel() {
    __shared__ int sb[SCAN_NB];
    __shared__ int s_carry;
    int t = threadIdx.x;
    if (t < SCAN_NB) sb[t] = g_bsum[t];
    __syncthreads();
    if (t == 0) {
        int myblk = (blockIdx.x * 256) / SCAN_BLK;
        int c = 0;
        for (int i = 0; i < myblk; i++) c += sb[i];
        s_carry = c;
    }
    __syncthreads();
    int i = blockIdx.x * 256 + t;
    if (i < N_NODES) {
        int o = g_off[i] + s_carry;
        g_off[i] = o;
        g_cursor[i] = o;
    }
    if (i == 0) g_off[N_NODES] = N_EDGES;
}

__global__ void fill_csr_kernel(const int4* __restrict__ src4,
                                const int4* __restrict__ dst4) {
    int i = blockIdx.x * blockDim.x + threadIdx.x;
    if (i < N_EDGES / 4) {
        int4 s = __ldg(&src4[i]);
        int4 d = __ldg(&dst4[i]);
        g_csr[atomicAdd(&g_cursor[d.x], 1)] = s.x;
        g_csr[atomicAdd(&g_cursor[d.y], 1)] = s.y;
        g_csr[atomicAdd(&g_cursor[d.z], 1)] = s.z;
        g_csr[atomicAdd(&g_cursor[d.w], 1)] = s.w;
    }
}

// ---------------- segment max pool: warp per dst node, fp16 in/out -----------
__global__ __launch_bounds__(256) void pool_kernel(const __half* __restrict__ P,
                                                   __half* __restrict__ Pl) {
    int gwarp = (blockIdx.x * 256 + threadIdx.x) >> 5;
    int lane  = threadIdx.x & 31;
    if (gwarp >= N_NODES) return;
    const __half2* P2 = (const __half2*)P;
    int s0 = g_off[gwarp];
    int s1 = g_off[gwarp + 1];
    __half2 m = __float2half2_rn(0.f);
    int e = s0;
    for (; e + 4 <= s1; e += 4) {
        int i0 = g_csr[e + 0], i1 = g_csr[e + 1];
        int i2 = g_csr[e + 2], i3 = g_csr[e + 3];
        __half2 a0 = __ldg(&P2[i0 * (F / 2) + lane]);
        __half2 a1 = __ldg(&P2[i1 * (F / 2) + lane]);
        __half2 a2 = __ldg(&P2[i2 * (F / 2) + lane]);
        __half2 a3 = __ldg(&P2[i3 * (F / 2) + lane]);
        m = __hmax2(m, __hmax2(__hmax2(a0, a1), __hmax2(a2, a3)));
    }
    for (; e < s1; e++) {
        int i = g_csr[e];
        m = __hmax2(m, __ldg(&P2[i * (F / 2) + lane]));
    }
    ((__half2*)Pl)[gwarp * (F / 2) + lane] = m;
}

// ------- GEMM: Y[N,DOUT] = act(X@Ws + PL(fp16)@Wn + b) -----------------------
template <int DOUT, int ACT>
__global__ __launch_bounds__(256) void gemm_out_kernel(
        const float* __restrict__ X, const __half* __restrict__ PL,
        const float* __restrict__ Ws, const float* __restrict__ Wn,
        const float* __restrict__ b, float* __restrict__ Y) {
    __shared__ ulonglong2 sWs[F * DOUT / 4];
    __shared__ ulonglong2 sWn[F * DOUT / 4];
    __shared__ ull sb[DOUT / 2];
    int t = threadIdx.x;
    const ulonglong2* Ws2 = (const ulonglong2*)Ws;
    const ulonglong2* Wn2 = (const ulonglong2*)Wn;
    for (int i = t; i < F * DOUT / 4; i += 256) { sWs[i] = Ws2[i]; sWn[i] = Wn2[i]; }
    if (t < DOUT / 2) sb[t] = ((const ull*)b)[t];
    __syncthreads();

    int r = blockIdx.x * 256 + t;
    if (r >= N_NODES) return;

    ull acc[DOUT / 2];
    #pragma unroll
    for (int j = 0; j < DOUT / 2; j++) acc[j] = sb[j];

    // self term
    const float4* xr = (const float4*)(X + (size_t)r * F);
    #pragma unroll
    for (int k4 = 0; k4 < F / 4; k4++) {
        float4 xv = __ldg(&xr[k4]);
        float xs[4] = {xv.x, xv.y, xv.z, xv.w};
        #pragma unroll
        for (int kk = 0; kk < 4; kk++) {
            int k = k4 * 4 + kk;
            ull xk = pack2(xs[kk]);
            #pragma unroll
            for (int j4 = 0; j4 < DOUT / 4; j4++) {
                ulonglong2 wv = sWs[k * (DOUT / 4) + j4];
                ffma2(acc[2 * j4 + 0], xk, wv.x);
                ffma2(acc[2 * j4 + 1], xk, wv.y);
            }
        }
    }
    // neighbor term: PL row as fp16x2, 8 x LDG.128
    const uint4* pr = (const uint4*)(PL + (size_t)r * F);
    #pragma unroll
    for (int j8 = 0; j8 < F / 8; j8++) {
        uint4 v = __ldg(&pr[j8]);
        unsigned hw[4] = {v.x, v.y, v.z, v.w};
        #pragma unroll
        for (int q = 0; q < 4; q++) {
            float2 f = __half22float2(*reinterpret_cast<__half2*>(&hw[q]));
            int k0 = j8 * 8 + 2 * q, k1 = k0 + 1;
            ull xa = pack2(f.x);
            ull xb = pack2(f.y);
            #pragma unroll
            for (int j4 = 0; j4 < DOUT / 4; j4++) {
                ulonglong2 wv = sWn[k0 * (DOUT / 4) + j4];
                ffma2(acc[2 * j4 + 0], xa, wv.x);
                ffma2(acc[2 * j4 + 1], xa, wv.y);
            }
            #pragma unroll
            for (int j4 = 0; j4 < DOUT / 4; j4++) {
                ulonglong2 wv = sWn[k1 * (DOUT / 4) + j4];
                ffma2(acc[2 * j4 + 0], xb, wv.x);
                ffma2(acc[2 * j4 + 1], xb, wv.y);
            }
        }
    }
    float4* yr = (float4*)(Y + (size_t)r * DOUT);
    #pragma unroll
    for (int j4 = 0; j4 < DOUT / 4; j4++) {
        float2 v0 = unpack2(acc[2 * j4 + 0]);
        float2 v1 = unpack2(acc[2 * j4 + 1]);
        float a0 = v0.x, a1 = v0.y, a2 = v1.x, a3 = v1.y;
        if (ACT == 1) {
            a0 = (a0 >= 0.f) ? a0 : NEG_SLOPE * a0;
            a1 = (a1 >= 0.f) ? a1 : NEG_SLOPE * a1;
            a2 = (a2 >= 0.f) ? a2 : NEG_SLOPE * a2;
            a3 = (a3 >= 0.f) ? a3 : NEG_SLOPE * a3;
        }
        float4 o; o.x = a0; o.y = a1; o.z = a2; o.w = a3;
        yr[j4] = o;
    }
}

// ---------------- launch -----------------------------------------------------
extern "C" void kernel_launch(void* const* d_in, const int* in_sizes, int n_in,
                              void* d_out, int out_size) {
    const float* in_feat = (const float*)d_in[0];
    const int*   src     = (const int*)d_in[1];
    const int*   dst     = (const int*)d_in[2];
    const float* W_pool1 = (const float*)d_in[3];
    const float* b_pool1 = (const float*)d_in[4];
    const float* W_self1 = (const float*)d_in[5];
    const float* W_neigh1= (const float*)d_in[6];
    const float* bias1   = (const float*)d_in[7];
    const float* W_pool2 = (const float*)d_in[8];
    const float* b_pool2 = (const float*)d_in[9];
    const float* W_self2 = (const float*)d_in[10];
    const float* W_neigh2= (const float*)d_in[11];
    const float* bias2   = (const float*)d_in[12];
    float* out = (float*)d_out;

    __half *dP, *dPl; float* dH;
    cudaGetSymbolAddress((void**)&dP, g_P);
    cudaGetSymbolAddress((void**)&dPl, g_Pl);
    cudaGetSymbolAddress((void**)&dH, g_H);

    const int POOLB = (N_NODES * 32 + 255) / 256;

    // K1: histogram (edge blocks) + layer-1 pool GEMM (node blocks), merged
    hist_gemm_kernel<<<EB4 + NB256, 256>>>((const int4*)dst,
                                           in_feat, W_pool1, b_pool1, dP);
    // CSR finalize
    scan1_kernel<<<SCAN_NB, SCAN_BLK>>>();
    scan3_kernel<<<NB256, 256>>>();
    fill_csr_kernel<<<EB4, 256>>>((const int4*)src, (const int4*)dst);

    // layer 1 (pool GEMM already done in K1)
    pool_kernel<<<POOLB, 256>>>(dP, dPl);
    gemm_out_kernel<64, 1><<<NB256, 256>>>(in_feat, dPl, W_self1, W_neigh1, bias1, dH);

    // layer 2
    gemm_pool_kernel<<<NB256, 256>>>(dH, W_pool2, b_pool2, dP);
    pool_kernel<<<POOLB, 256>>>(dP, dPl);
    gemm_out_kernel<16, 0><<<NB256, 256>>>(dH, dPl, W_self2, W_neigh2, bias2, out);
}